// round 1
// baseline (speedup 1.0000x reference)
#include <cuda_runtime.h>
#include <cuda_fp16.h>

// Problem constants
#define BB 8
#define TT 4096
#define DD 512
#define OO 512
static constexpr int M    = BB * TT;     // 32768 rows
static constexpr int K    = 1024;        // 2 taps * D
static constexpr int NTOT = 1536;        // 3 gates * O
static constexpr int BM = 128, BN = 64, BK = 16;
static constexpr int NCH = BB * OO;      // 4096 scan channels
static constexpr int CH  = 64;           // chunks per sequence
static constexpr int TC  = TT / CH;      // 64 steps per chunk

// Scratch (static device arrays: allocation-free per harness rules)
__device__ float g_Wc[(size_t)K * NTOT];          // packed, fp16-rounded weights (6 MB)
__device__ float g_act[(size_t)3 * M * OO];       // z | f | o activations (192 MB)
__device__ float g_P[CH * NCH];
__device__ float g_Q[CH * NCH];
__device__ float g_H[CH * NCH];

// ---------------------------------------------------------------------------
// Pack W_{z,f,o}[win,d,o] -> Wc[k, n], k = tap*512 + d, n = gate*512 + o.
// Values rounded to fp16 to emulate tensor-core f16 input numerics.
// ---------------------------------------------------------------------------
__global__ void prep_w_kernel(const float* __restrict__ Wz,
                              const float* __restrict__ Wf,
                              const float* __restrict__ Wo) {
    int i = blockIdx.x * blockDim.x + threadIdx.x;
    if (i >= K * NTOT) return;
    int k = i / NTOT, n = i - k * NTOT;
    int g = n >> 9, o = n & 511;
    int w = k >> 9, d = k & 511;
    const float* W = (g == 0) ? Wz : ((g == 1) ? Wf : Wo);
    float v = W[((size_t)w * DD + d) * OO + o];
    g_Wc[i] = __half2float(__float2half_rn(v));
}

// ---------------------------------------------------------------------------
// GEMM (M x K) * (K x NTOT) with fused bias + activation.
// A[m,k] = (k<512) ? x[m-1, k]  (0 at t==0)  : x[m, k-512], fp16-rounded.
// Epilogue: gate 0 -> tanh, gates 1,2 -> sigmoid; store into g_act.
// ---------------------------------------------------------------------------
__global__ __launch_bounds__(256) void gemm_act_kernel(
    const float* __restrict__ x, const float* __restrict__ bz,
    const float* __restrict__ bf, const float* __restrict__ bo) {
    __shared__ float As[BK][132];   // padded stride to tame store conflicts
    __shared__ float Bs[BK][BN];

    const int tid = threadIdx.x;
    const int m0  = blockIdx.x * BM;
    const int n0  = blockIdx.y * BN;
    const int gate = n0 >> 9;       // BN=64 divides 512 -> uniform per CTA
    const int tx = tid & 15, ty = tid >> 4;

    float acc[8][4];
#pragma unroll
    for (int i = 0; i < 8; i++)
#pragma unroll
        for (int j = 0; j < 4; j++) acc[i][j] = 0.f;

    for (int k0 = 0; k0 < K; k0 += BK) {
        const int tap = k0 >> 9;    // BK=16 tiles never straddle the tap split
        const int d0  = k0 & 511;
        // --- load A tile (128 x 16), 2 float4 per thread, transpose to As[k][m]
#pragma unroll
        for (int l = 0; l < 2; l++) {
            int lin = tid + 256 * l;          // 0..511
            int ml  = lin >> 2;               // 0..127
            int k4  = lin & 3;                // 0..3 (group of 4 k)
            int m   = m0 + ml;
            int t   = m & (TT - 1);
            float4 v = make_float4(0.f, 0.f, 0.f, 0.f);
            const float* src;
            bool ok;
            if (tap == 1) { src = x + (size_t)m * DD + (d0 + k4 * 4); ok = true; }
            else          { src = x + (size_t)(m - 1) * DD + (d0 + k4 * 4); ok = (t > 0); }
            if (ok) v = *reinterpret_cast<const float4*>(src);
            v.x = __half2float(__float2half_rn(v.x));
            v.y = __half2float(__float2half_rn(v.y));
            v.z = __half2float(__float2half_rn(v.z));
            v.w = __half2float(__float2half_rn(v.w));
            As[k4 * 4 + 0][ml] = v.x;
            As[k4 * 4 + 1][ml] = v.y;
            As[k4 * 4 + 2][ml] = v.z;
            As[k4 * 4 + 3][ml] = v.w;
        }
        // --- load B tile (16 x 64), 1 float4 per thread
        {
            int row = tid >> 4;
            int c   = (tid & 15) * 4;
            float4 v = *reinterpret_cast<const float4*>(
                g_Wc + (size_t)(k0 + row) * NTOT + n0 + c);
            Bs[row][c + 0] = v.x; Bs[row][c + 1] = v.y;
            Bs[row][c + 2] = v.z; Bs[row][c + 3] = v.w;
        }
        __syncthreads();
#pragma unroll
        for (int k = 0; k < BK; k++) {
            float4 a0 = *reinterpret_cast<const float4*>(&As[k][ty * 8]);
            float4 a1 = *reinterpret_cast<const float4*>(&As[k][ty * 8 + 4]);
            float4 b4 = *reinterpret_cast<const float4*>(&Bs[k][tx * 4]);
            float a[8] = {a0.x, a0.y, a0.z, a0.w, a1.x, a1.y, a1.z, a1.w};
            float b[4] = {b4.x, b4.y, b4.z, b4.w};
#pragma unroll
            for (int i = 0; i < 8; i++)
#pragma unroll
                for (int j = 0; j < 4; j++)
                    acc[i][j] = fmaf(a[i], b[j], acc[i][j]);
        }
        __syncthreads();
    }

    // --- epilogue: bias + activation, float4 stores
    const float* bptr = (gate == 0) ? bz : ((gate == 1) ? bf : bo);
    const int o0 = (n0 & 511) + tx * 4;
    const size_t gbase = (size_t)gate * M * OO;
#pragma unroll
    for (int i = 0; i < 8; i++) {
        int m = m0 + ty * 8 + i;
        float4 r;
        float* rp = &r.x;
#pragma unroll
        for (int j = 0; j < 4; j++) {
            float v = acc[i][j] + bptr[o0 + j];
            if (gate == 0) v = tanhf(v);
            else           v = 1.f / (1.f + expf(-v));
            rp[j] = v;
        }
        *reinterpret_cast<float4*>(g_act + gbase + (size_t)m * OO + o0) = r;
    }
}

// ---------------------------------------------------------------------------
// Chunked linear-recurrence scan: h_t = f_t*h_{t-1} + (1-f_t)*z_t
// Pass 1: per-chunk affine summary (P = prod f, Q = chunk-local scan from 0)
// ---------------------------------------------------------------------------
__global__ void scan1_kernel() {
    int ch    = blockIdx.x * blockDim.x + threadIdx.x;   // 0..4095
    int chunk = blockIdx.y;
    int b = ch >> 9, o = ch & 511;
    size_t base = (size_t)(b * TT + chunk * TC) * OO + o;
    const float* Z = g_act;
    const float* F = g_act + (size_t)M * OO;
    float h = 0.f, P = 1.f;
#pragma unroll 4
    for (int i = 0; i < TC; i++) {
        float f = F[base + (size_t)i * OO];
        float z = Z[base + (size_t)i * OO];
        h = f * h + (1.f - f) * z;
        P *= f;
    }
    g_P[chunk * NCH + ch] = P;
    g_Q[chunk * NCH + ch] = h;
}

// Pass 2: sequential combine of the 64 chunk summaries -> chunk start states
__global__ void scan2_kernel() {
    int ch = blockIdx.x * blockDim.x + threadIdx.x;
    float hs = 0.f;
#pragma unroll
    for (int c = 0; c < CH; c++) {
        g_H[c * NCH + ch] = hs;
        hs = g_P[c * NCH + ch] * hs + g_Q[c * NCH + ch];
    }
}

// Pass 3: re-scan each chunk with the correct start state, apply output gate
__global__ void scan3_kernel(float* __restrict__ out) {
    int ch    = blockIdx.x * blockDim.x + threadIdx.x;
    int chunk = blockIdx.y;
    int b = ch >> 9, o = ch & 511;
    size_t base = (size_t)(b * TT + chunk * TC) * OO + o;
    const float* Z  = g_act;
    const float* F  = g_act + (size_t)M * OO;
    const float* Og = g_act + (size_t)2 * M * OO;
    float h = g_H[chunk * NCH + ch];
#pragma unroll 4
    for (int i = 0; i < TC; i++) {
        float f = F[base + (size_t)i * OO];
        float z = Z[base + (size_t)i * OO];
        h = f * h + (1.f - f) * z;
        out[base + (size_t)i * OO] = Og[base + (size_t)i * OO] * h;
    }
}

// ---------------------------------------------------------------------------
extern "C" void kernel_launch(void* const* d_in, const int* in_sizes, int n_in,
                              void* d_out, int out_size) {
    const float* x  = (const float*)d_in[0];
    const float* Wz = (const float*)d_in[1];
    const float* Wf = (const float*)d_in[2];
    const float* Wo = (const float*)d_in[3];
    const float* bz = (const float*)d_in[4];
    const float* bf = (const float*)d_in[5];
    const float* bo = (const float*)d_in[6];
    float* out = (float*)d_out;

    prep_w_kernel<<<(K * NTOT + 255) / 256, 256>>>(Wz, Wf, Wo);
    dim3 gg(M / BM, NTOT / BN);
    gemm_act_kernel<<<gg, 256>>>(x, bz, bf, bo);
    scan1_kernel<<<dim3(NCH / 256, CH), 256>>>();
    scan2_kernel<<<NCH / 256, 256>>>();
    scan3_kernel<<<dim3(NCH / 256, CH), 256>>>(out);
}

// round 4
// speedup vs baseline: 6.2523x; 6.2523x over previous
#include <cuda_runtime.h>
#include <cuda_fp16.h>
#include <cstdint>

// Problem constants
#define BB 8
#define TT 4096
#define DD 512
#define OO 512
static constexpr int M    = BB * TT;     // 32768
static constexpr int K    = 1024;        // 2 taps * D
static constexpr int NTOT = 1536;        // 3 gates * O
static constexpr int NCH  = BB * OO;     // 4096 scan channels
static constexpr int CH   = 64;          // chunks per sequence
static constexpr int TC   = TT / CH;     // 64 steps per chunk

// GEMM tiling
static constexpr int BM = 128, BN = 128, BK = 64;   // BK in halves (128 B per row)
static constexpr int KCHUNKS = K / BK;              // 16
static constexpr int STAGE_BYTES = 32768;           // A(16KB) + B(16KB)
static constexpr int SMEM_SZ = 2 * STAGE_BYTES;     // 64 KB

// Scratch (static device arrays — allocation-free per harness rules)
__device__ __half g_Ah[(size_t)M * K];              // 64 MB fp16 A with tap shift
__device__ __half g_Wh[(size_t)NTOT * K];           // 3 MB  B operand [N,K] K-major
__device__ float  g_act[(size_t)3 * M * OO];        // z | f | o (192 MB)
__device__ float  g_P[CH * NCH];
__device__ float  g_Q[CH * NCH];
__device__ float  g_H[CH * NCH];

// ---------------------------------------------------------------------------
// PTX helpers (sm_80+ portable: cp.async, ldmatrix, mma.sync)
// ---------------------------------------------------------------------------
__device__ __forceinline__ uint32_t smem_u32(const void* p) {
    uint32_t a;
    asm("{ .reg .u64 t; cvta.to.shared.u64 t, %1; cvt.u32.u64 %0, t; }" : "=r"(a) : "l"(p));
    return a;
}
#define CP_ASYNC16(saddr, gptr) \
    asm volatile("cp.async.cg.shared.global [%0], [%1], 16;" :: "r"(saddr), "l"(gptr) : "memory")
#define CP_COMMIT() asm volatile("cp.async.commit_group;" ::: "memory")
#define CP_WAIT1()  asm volatile("cp.async.wait_group 1;" ::: "memory")
#define CP_WAIT0()  asm volatile("cp.async.wait_group 0;" ::: "memory")

__device__ __forceinline__ void ldsm_x4(uint32_t& r0, uint32_t& r1, uint32_t& r2,
                                        uint32_t& r3, uint32_t addr) {
    asm volatile("ldmatrix.sync.aligned.m8n8.x4.shared.b16 {%0,%1,%2,%3}, [%4];"
                 : "=r"(r0), "=r"(r1), "=r"(r2), "=r"(r3) : "r"(addr));
}
__device__ __forceinline__ void mma16816(float* c, const uint32_t* a, const uint32_t* b) {
    asm volatile(
        "mma.sync.aligned.m16n8k16.row.col.f32.f16.f16.f32 "
        "{%0,%1,%2,%3}, {%4,%5,%6,%7}, {%8,%9}, {%0,%1,%2,%3};"
        : "+f"(c[0]), "+f"(c[1]), "+f"(c[2]), "+f"(c[3])
        : "r"(a[0]), "r"(a[1]), "r"(a[2]), "r"(a[3]), "r"(b[0]), "r"(b[1]));
}

// ---------------------------------------------------------------------------
// Prep: pack weights -> g_Wh[n][k] fp16  (n = gate*512 + o, k = tap*512 + d)
// ---------------------------------------------------------------------------
__global__ void prep_w_kernel(const float* __restrict__ Wz,
                              const float* __restrict__ Wf,
                              const float* __restrict__ Wo) {
    int i = blockIdx.x * blockDim.x + threadIdx.x;
    if (i >= NTOT * K) return;
    int n = i >> 10, k = i & 1023;
    int g = n >> 9, o = n & 511;
    int w = k >> 9, d = k & 511;
    const float* W = (g == 0) ? Wz : ((g == 1) ? Wf : Wo);
    g_Wh[i] = __float2half_rn(W[((size_t)w * DD + d) * OO + o]);
}

// Prep: build fp16 A matrix with tap-0 shift. A[m][k<512]=x[m-1], A[m][k>=512]=x[m].
__global__ void prep_a_kernel(const float* __restrict__ x) {
    int idx = blockIdx.x * blockDim.x + threadIdx.x;   // one 16B (8-half) segment
    if (idx >= M * (K / 8)) return;
    int m = idx >> 7, seg = idx & 127;
    int k0 = seg * 8;
    int t = m & (TT - 1);
    bool tap0 = (k0 < 512);
    __half h[8];
    if (tap0 && t == 0) {
#pragma unroll
        for (int j = 0; j < 8; j++) h[j] = __float2half_rn(0.f);
    } else {
        int row = tap0 ? (m - 1) : m;
        int d0  = tap0 ? k0 : (k0 - 512);
        const float* src = x + (size_t)row * DD + d0;
        float4 v0 = *reinterpret_cast<const float4*>(src);
        float4 v1 = *reinterpret_cast<const float4*>(src + 4);
        h[0] = __float2half_rn(v0.x); h[1] = __float2half_rn(v0.y);
        h[2] = __float2half_rn(v0.z); h[3] = __float2half_rn(v0.w);
        h[4] = __float2half_rn(v1.x); h[5] = __float2half_rn(v1.y);
        h[6] = __float2half_rn(v1.z); h[7] = __float2half_rn(v1.w);
    }
    *reinterpret_cast<uint4*>(&g_Ah[(size_t)m * K + k0]) =
        *reinterpret_cast<const uint4*>(h);
}

// ---------------------------------------------------------------------------
// mma.sync fp16 GEMM with fused bias + activation epilogue.
// C[M,NTOT] = A[M,K] * B[NTOT,K]^T ; 8 warps, warp tile 64x32.
// SMEM tiles [128][64] halves, SW128 swizzle (conflict-free ldmatrix).
// ---------------------------------------------------------------------------
__global__ __launch_bounds__(256, 2) void gemm_mma_kernel(
    const float* __restrict__ bz, const float* __restrict__ bf,
    const float* __restrict__ bo) {
    extern __shared__ char smem[];
    const uint32_t sb = smem_u32(smem);
    const int tid  = threadIdx.x;
    const int lane = tid & 31;
    const int warp = tid >> 5;
    const int wm = warp & 1;        // m offset wm*64
    const int wn = warp >> 1;       // n offset wn*32
    const int m0 = blockIdx.x * BM;
    const int n0 = blockIdx.y * BN;
    const int gate = n0 >> 9;       // BN=128 divides 512 -> uniform per CTA

    const __half* gA = g_Ah + (size_t)m0 * K;
    const __half* gB = g_Wh + (size_t)n0 * K;

    float acc[4][4][4];
#pragma unroll
    for (int i = 0; i < 4; i++)
#pragma unroll
        for (int j = 0; j < 4; j++)
#pragma unroll
            for (int r = 0; r < 4; r++) acc[i][j][r] = 0.f;

    // stage loader: A at st*32768, B at st*32768+16384
    auto load_stage = [&](int st, int kc) {
        uint32_t abase = sb + st * STAGE_BYTES;
#pragma unroll
        for (int l = 0; l < 4; l++) {
            int idx = tid + l * 256;
            int row = idx >> 3, c = idx & 7;
            uint32_t sw = abase + row * 128 + (((c) ^ (row & 7)) << 4);
            CP_ASYNC16(sw, gA + (size_t)row * K + kc * BK + c * 8);
        }
        uint32_t bbase = abase + 16384;
#pragma unroll
        for (int l = 0; l < 4; l++) {
            int idx = tid + l * 256;
            int row = idx >> 3, c = idx & 7;
            uint32_t sw = bbase + row * 128 + (((c) ^ (row & 7)) << 4);
            CP_ASYNC16(sw, gB + (size_t)row * K + kc * BK + c * 8);
        }
    };

    load_stage(0, 0); CP_COMMIT();
    load_stage(1, 1); CP_COMMIT();

    // per-lane ldmatrix row indices (constant across iterations)
    const int arow  = wm * 64 + (lane & 15);          // + mi*16
    const int achk0 = (lane >> 4);                    // +2s
    const int brow  = wn * 32 + (lane & 7) + ((lane >> 4) << 3);   // + ni2*16
    const int bchk0 = (lane >> 3) & 1;                // +2s
    const int asw   = lane & 7;                       // row&7 for swizzle (both A,B)

    for (int kc = 0; kc < KCHUNKS; kc++) {
        if (kc == KCHUNKS - 1) { CP_WAIT0(); } else { CP_WAIT1(); }
        __syncthreads();
        const uint32_t stg = sb + (kc & 1) * STAGE_BYTES;
#pragma unroll
        for (int s = 0; s < 4; s++) {                 // 4 x k16 within BK=64
            uint32_t a[4][4];
#pragma unroll
            for (int mi = 0; mi < 4; mi++) {
                uint32_t addr = stg + (arow + mi * 16) * 128 +
                                (((2 * s + achk0) ^ asw) << 4);
                ldsm_x4(a[mi][0], a[mi][1], a[mi][2], a[mi][3], addr);
            }
            uint32_t b[4][2];
#pragma unroll
            for (int ni2 = 0; ni2 < 2; ni2++) {
                uint32_t r0, r1, r2, r3;
                uint32_t addr = stg + 16384 + (brow + ni2 * 16) * 128 +
                                (((2 * s + bchk0) ^ asw) << 4);
                ldsm_x4(r0, r1, r2, r3, addr);
                b[ni2 * 2 + 0][0] = r0; b[ni2 * 2 + 0][1] = r1;
                b[ni2 * 2 + 1][0] = r2; b[ni2 * 2 + 1][1] = r3;
            }
#pragma unroll
            for (int mi = 0; mi < 4; mi++)
#pragma unroll
                for (int ni = 0; ni < 4; ni++)
                    mma16816(acc[mi][ni], a[mi], b[ni]);
        }
        __syncthreads();
        if (kc + 2 < KCHUNKS) { load_stage(kc & 1, kc + 2); CP_COMMIT(); }
    }

    // Epilogue: bias + activation, float2 stores straight to g_act
    const float* bptr = (gate == 0) ? bz : ((gate == 1) ? bf : bo);
    float* gbase = g_act + (size_t)gate * M * OO;
    const int ogb = (n0 & 511) + wn * 32;
#pragma unroll
    for (int mi = 0; mi < 4; mi++) {
#pragma unroll
        for (int rh = 0; rh < 2; rh++) {
            int row = m0 + wm * 64 + mi * 16 + (lane >> 2) + rh * 8;
            float* drow = gbase + (size_t)row * OO;
#pragma unroll
            for (int ni = 0; ni < 4; ni++) {
                int col = ogb + ni * 8 + 2 * (lane & 3);
                float u0 = acc[mi][ni][rh * 2 + 0] + bptr[col + 0];
                float u1 = acc[mi][ni][rh * 2 + 1] + bptr[col + 1];
                float2 v;
                if (gate == 0) { v.x = tanhf(u0); v.y = tanhf(u1); }
                else { v.x = 1.f / (1.f + expf(-u0)); v.y = 1.f / (1.f + expf(-u1)); }
                *reinterpret_cast<float2*>(drow + col) = v;
            }
        }
    }
}

// ---------------------------------------------------------------------------
// Chunked linear-recurrence scan: h_t = f_t*h_{t-1} + (1-f_t)*z_t
// ---------------------------------------------------------------------------
__global__ void scan1_kernel() {
    int ch    = blockIdx.x * blockDim.x + threadIdx.x;   // 0..4095
    int chunk = blockIdx.y;
    int b = ch >> 9, o = ch & 511;
    size_t base = (size_t)(b * TT + chunk * TC) * OO + o;
    const float* Z = g_act;
    const float* F = g_act + (size_t)M * OO;
    float h = 0.f, P = 1.f;
#pragma unroll 4
    for (int i = 0; i < TC; i++) {
        float f = F[base + (size_t)i * OO];
        float z = Z[base + (size_t)i * OO];
        h = f * h + (1.f - f) * z;
        P *= f;
    }
    g_P[chunk * NCH + ch] = P;
    g_Q[chunk * NCH + ch] = h;
}

__global__ void scan2_kernel() {
    int ch = blockIdx.x * blockDim.x + threadIdx.x;
    float hs = 0.f;
#pragma unroll
    for (int c = 0; c < CH; c++) {
        g_H[c * NCH + ch] = hs;
        hs = g_P[c * NCH + ch] * hs + g_Q[c * NCH + ch];
    }
}

__global__ void scan3_kernel(float* __restrict__ out) {
    int ch    = blockIdx.x * blockDim.x + threadIdx.x;
    int chunk = blockIdx.y;
    int b = ch >> 9, o = ch & 511;
    size_t base = (size_t)(b * TT + chunk * TC) * OO + o;
    const float* Z  = g_act;
    const float* F  = g_act + (size_t)M * OO;
    const float* Og = g_act + (size_t)2 * M * OO;
    float h = g_H[chunk * NCH + ch];
#pragma unroll 4
    for (int i = 0; i < TC; i++) {
        float f = F[base + (size_t)i * OO];
        float z = Z[base + (size_t)i * OO];
        h = f * h + (1.f - f) * z;
        out[base + (size_t)i * OO] = Og[base + (size_t)i * OO] * h;
    }
}

// ---------------------------------------------------------------------------
extern "C" void kernel_launch(void* const* d_in, const int* in_sizes, int n_in,
                              void* d_out, int out_size) {
    const float* x  = (const float*)d_in[0];
    const float* Wz = (const float*)d_in[1];
    const float* Wf = (const float*)d_in[2];
    const float* Wo = (const float*)d_in[3];
    const float* bz = (const float*)d_in[4];
    const float* bf = (const float*)d_in[5];
    const float* bo = (const float*)d_in[6];
    float* out = (float*)d_out;

    static bool attr_set = false;
    if (!attr_set) {
        cudaFuncSetAttribute(gemm_mma_kernel,
                             cudaFuncAttributeMaxDynamicSharedMemorySize, SMEM_SZ);
        attr_set = true;
    }

    prep_w_kernel<<<(NTOT * K + 255) / 256, 256>>>(Wz, Wf, Wo);
    prep_a_kernel<<<(M * (K / 8) + 255) / 256, 256>>>(x);
    gemm_mma_kernel<<<dim3(M / BM, NTOT / BN), 256, SMEM_SZ>>>(bz, bf, bo);
    scan1_kernel<<<dim3(NCH / 256, CH), 256>>>();
    scan2_kernel<<<NCH / 256, 256>>>();
    scan3_kernel<<<dim3(NCH / 256, CH), 256>>>(out);
}